// round 3
// baseline (speedup 1.0000x reference)
#include <cuda_runtime.h>
#include <math.h>

// Swin block: B=32, H=W=112, C=96, NH=3, WS=7, SHIFT=3
#define B_      32
#define H_      112
#define W_      112
#define C_      96
#define NH_     3
#define WS_     7
#define SHIFT_  3
#define N_      49          // WS*WS
#define HD_     32          // C/NH
#define NWH_    16          // H/WS
#define NW_IMG  256         // per-image windows
#define NWIN    8192        // B * NW_IMG
#define TOK     401408      // B*H*W
#define HID_    384

// ---------------- scratch (device globals; no allocations allowed) ---------
__device__ float g_qkv[(size_t)3 * NWIN * NH_ * N_ * HD_];   // q | k | v
__device__ float g_ao[(size_t)NWIN * N_ * C_];               // head-merged attn output
__device__ float g_x1[(size_t)TOK * C_];                     // shortcut + attn branch

#define QKV_SEG ((size_t)NWIN * NH_ * N_ * HD_)

// ---------------------------------------------------------------------------
// K1: LN1 + cyclic shift + window partition + QKV GEMM (49x96 @ 96x288)
// one block per window, 512 threads. LN by 16 warps, GEMM microtile 7x4.
// ---------------------------------------------------------------------------
__global__ __launch_bounds__(512) void k1_ln_qkv(
    const float* __restrict__ x,
    const float* __restrict__ n1g, const float* __restrict__ n1b,
    const float* __restrict__ qkv_w, const float* __restrict__ qkv_b)
{
    __shared__ float sx[N_][C_];
    const int win = blockIdx.x;
    const int b = win >> 8;
    const int wi = win & 255;
    const int wh = wi >> 4, ww = wi & 15;
    const int tid = threadIdx.x;
    const int warp = tid >> 5, lane = tid & 31;

    // ---- LN1 over shifted/windowed tokens, result into smem --------------
    for (int n = warp; n < N_; n += 16) {
        const int i = n / 7, j = n % 7;
        const int sh = (wh * 7 + i + SHIFT_) % H_;
        const int sw = (ww * 7 + j + SHIFT_) % W_;
        const float* row = x + (size_t)(b * H_ * W_ + sh * W_ + sw) * C_;
        float v0 = row[lane], v1 = row[lane + 32], v2 = row[lane + 64];
        float s = v0 + v1 + v2;
        float ss = v0 * v0 + v1 * v1 + v2 * v2;
        #pragma unroll
        for (int o = 16; o > 0; o >>= 1) {
            s  += __shfl_xor_sync(0xffffffffu, s, o);
            ss += __shfl_xor_sync(0xffffffffu, ss, o);
        }
        const float mean = s * (1.f / 96.f);
        const float var  = ss * (1.f / 96.f) - mean * mean;
        const float rstd = rsqrtf(var + 1e-5f);
        sx[n][lane]      = (v0 - mean) * rstd * n1g[lane]      + n1b[lane];
        sx[n][lane + 32] = (v1 - mean) * rstd * n1g[lane + 32] + n1b[lane + 32];
        sx[n][lane + 64] = (v2 - mean) * rstd * n1g[lane + 64] + n1b[lane + 64];
    }
    __syncthreads();

    if (tid >= 504) return;
    const int tr = tid / 72;          // 0..6  -> rows tr*7 .. tr*7+6
    const int tc = tid % 72;          // 0..71 -> cols tc*4 .. tc*4+3
    const int col0 = tc * 4;

    float acc[7][4];
    #pragma unroll
    for (int r = 0; r < 7; r++)
        #pragma unroll
        for (int c = 0; c < 4; c++) acc[r][c] = 0.f;

    #pragma unroll 2
    for (int k = 0; k < C_; k += 4) {
        float4 a[7];
        #pragma unroll
        for (int r = 0; r < 7; r++)
            a[r] = *(const float4*)&sx[tr * 7 + r][k];
        float4 w[4];
        #pragma unroll
        for (int c = 0; c < 4; c++)
            w[c] = *(const float4*)&qkv_w[(col0 + c) * C_ + k];
        #pragma unroll
        for (int r = 0; r < 7; r++)
            #pragma unroll
            for (int c = 0; c < 4; c++)
                acc[r][c] += a[r].x * w[c].x + a[r].y * w[c].y +
                             a[r].z * w[c].z + a[r].w * w[c].w;
    }

    #pragma unroll
    for (int c = 0; c < 4; c++) {
        const int col = col0 + c;
        const int which = col / 96;            // 0=q 1=k 2=v
        const int head = (col % 96) / 32;
        const int hd = col & 31;
        const float bb = qkv_b[col];
        const float scale = (which == 0) ? 0.17677669529663687f : 1.f;   // HD^-0.5
        float* dst = g_qkv + (size_t)which * QKV_SEG;
        const size_t base = ((size_t)win * NH_ + head) * N_ * HD_ + hd;
        #pragma unroll
        for (int r = 0; r < 7; r++) {
            const int n = tr * 7 + r;
            dst[base + (size_t)n * HD_] = (acc[r][c] + bb) * scale;
        }
    }
}

// ---------------------------------------------------------------------------
// K2: attention per (window, head). 64 threads; thread i = query row i.
// scores + softmax fully in registers (N=49).
// ---------------------------------------------------------------------------
__global__ __launch_bounds__(64) void k2_attn(
    const float* __restrict__ attn_mask,
    const int* __restrict__ rel_index,
    const float* __restrict__ rel_tab)
{
    __shared__ float sk[N_][HD_];
    __shared__ float sv[N_][HD_];
    __shared__ float sbm[N_][N_];     // bias + mask
    const int win = blockIdx.x;
    const int head = blockIdx.y;
    const int tid = threadIdx.x;

    const float* kp = g_qkv + QKV_SEG + ((size_t)win * NH_ + head) * N_ * HD_;
    const float* vp = g_qkv + 2 * QKV_SEG + ((size_t)win * NH_ + head) * N_ * HD_;
    for (int i = tid; i < N_ * HD_; i += 64) {
        (&sk[0][0])[i] = kp[i];
        (&sv[0][0])[i] = vp[i];
    }
    const float* mp = attn_mask + (size_t)(win & 255) * N_ * N_;
    for (int i = tid; i < N_ * N_; i += 64)
        (&sbm[0][0])[i] = rel_tab[rel_index[i] * NH_ + head] + mp[i];
    __syncthreads();

    if (tid >= N_) return;
    const float* qp = g_qkv + (((size_t)win * NH_ + head) * N_ + tid) * HD_;
    float q[HD_];
    #pragma unroll
    for (int d = 0; d < HD_; d++) q[d] = qp[d];

    float s[N_];
    float mx = -1e30f;
    #pragma unroll
    for (int j = 0; j < N_; j++) {
        float acc = sbm[tid][j];
        #pragma unroll
        for (int d = 0; d < HD_; d++) acc += q[d] * sk[j][d];
        s[j] = acc;
        mx = fmaxf(mx, acc);
    }
    float denom = 0.f;
    #pragma unroll
    for (int j = 0; j < N_; j++) { s[j] = __expf(s[j] - mx); denom += s[j]; }
    const float inv = 1.f / denom;

    float o[HD_];
    #pragma unroll
    for (int d = 0; d < HD_; d++) o[d] = 0.f;
    #pragma unroll
    for (int j = 0; j < N_; j++) {
        const float p = s[j];
        #pragma unroll
        for (int d = 0; d < HD_; d++) o[d] += p * sv[j][d];
    }
    float* op = g_ao + ((size_t)win * N_ + tid) * C_ + head * HD_;
    #pragma unroll
    for (int d = 0; d < HD_; d++) op[d] = o[d] * inv;
}

// ---------------------------------------------------------------------------
// K3: proj GEMM (49x96 @ 96x96) + window reverse + unshift + residual -> x1
// one block per window, 192 threads, microtile 7x4 (168 active).
// ---------------------------------------------------------------------------
__global__ __launch_bounds__(192) void k3_proj(
    const float* __restrict__ x,
    const float* __restrict__ proj_w, const float* __restrict__ proj_b)
{
    __shared__ float sa[N_][C_];
    const int win = blockIdx.x;
    const int b = win >> 8;
    const int wi = win & 255;
    const int wh = wi >> 4, ww = wi & 15;
    const int tid = threadIdx.x;

    const float* ap = g_ao + (size_t)win * N_ * C_;
    for (int i = tid; i < N_ * C_; i += 192) (&sa[0][0])[i] = ap[i];
    __syncthreads();

    if (tid >= 168) return;
    const int tr = tid / 24;        // rows tr*7..
    const int tc = tid % 24;        // cols tc*4..
    const int col0 = tc * 4;

    float acc[7][4];
    #pragma unroll
    for (int r = 0; r < 7; r++)
        #pragma unroll
        for (int c = 0; c < 4; c++) acc[r][c] = 0.f;

    #pragma unroll 2
    for (int k = 0; k < C_; k += 4) {
        float4 a[7];
        #pragma unroll
        for (int r = 0; r < 7; r++)
            a[r] = *(const float4*)&sa[tr * 7 + r][k];
        float4 w[4];
        #pragma unroll
        for (int c = 0; c < 4; c++)
            w[c] = *(const float4*)&proj_w[(col0 + c) * C_ + k];
        #pragma unroll
        for (int r = 0; r < 7; r++)
            #pragma unroll
            for (int c = 0; c < 4; c++)
                acc[r][c] += a[r].x * w[c].x + a[r].y * w[c].y +
                             a[r].z * w[c].z + a[r].w * w[c].w;
    }

    #pragma unroll
    for (int r = 0; r < 7; r++) {
        const int n = tr * 7 + r;
        const int i = n / 7, j = n % 7;
        const int sh = (wh * 7 + i + SHIFT_) % H_;
        const int sw = (ww * 7 + j + SHIFT_) % W_;
        const size_t tok = (size_t)(b * H_ * W_ + sh * W_ + sw);
        float4 xr = *(const float4*)&x[tok * C_ + col0];
        float4 o;
        o.x = xr.x + acc[r][0] + proj_b[col0 + 0];
        o.y = xr.y + acc[r][1] + proj_b[col0 + 1];
        o.z = xr.z + acc[r][2] + proj_b[col0 + 2];
        o.w = xr.w + acc[r][3] + proj_b[col0 + 3];
        *(float4*)&g_x1[tok * C_ + col0] = o;
    }
}

// ---------------------------------------------------------------------------
// K4: LN2 + FC1 + GELU + FC2 + residual. 16 tokens/block, 384 threads.
// STATIC shared memory: 16*96*4 + 16*384*4 = 30720 B (< 48KB, no opt-in).
// ---------------------------------------------------------------------------
__global__ __launch_bounds__(384) void k4_mlp(
    const float* __restrict__ n2g, const float* __restrict__ n2b,
    const float* __restrict__ f1w, const float* __restrict__ f1b,
    const float* __restrict__ f2w, const float* __restrict__ f2b,
    float* __restrict__ out)
{
    __shared__ float sxn[16][C_];       // LN2 output
    __shared__ float shh[16][HID_];     // GELU(FC1) output
    const int t0 = blockIdx.x * 16;
    const int tid = threadIdx.x;
    const int warp = tid >> 5, lane = tid & 31;   // 12 warps

    // ---- LN2 -------------------------------------------------------------
    for (int t = warp; t < 16; t += 12) {
        const float* row = g_x1 + (size_t)(t0 + t) * C_;
        float v0 = row[lane], v1 = row[lane + 32], v2 = row[lane + 64];
        float s = v0 + v1 + v2;
        float ss = v0 * v0 + v1 * v1 + v2 * v2;
        #pragma unroll
        for (int o = 16; o > 0; o >>= 1) {
            s  += __shfl_xor_sync(0xffffffffu, s, o);
            ss += __shfl_xor_sync(0xffffffffu, ss, o);
        }
        const float mean = s * (1.f / 96.f);
        const float var  = ss * (1.f / 96.f) - mean * mean;
        const float rstd = rsqrtf(var + 1e-5f);
        sxn[t][lane]      = (v0 - mean) * rstd * n2g[lane]      + n2b[lane];
        sxn[t][lane + 32] = (v1 - mean) * rstd * n2g[lane + 32] + n2b[lane + 32];
        sxn[t][lane + 64] = (v2 - mean) * rstd * n2g[lane + 64] + n2b[lane + 64];
    }
    __syncthreads();

    // ---- FC1 (16x96 @ 96x384) + GELU, microtile 2x8 -----------------------
    {
        const int tr = tid / 48;        // 0..7 -> rows tr*2..
        const int tc = tid % 48;        // cols tc*8..
        const int col0 = tc * 8;
        float acc[2][8];
        #pragma unroll
        for (int r = 0; r < 2; r++)
            #pragma unroll
            for (int c = 0; c < 8; c++) acc[r][c] = 0.f;

        #pragma unroll 1
        for (int k = 0; k < C_; k += 4) {
            float4 a[2];
            #pragma unroll
            for (int r = 0; r < 2; r++)
                a[r] = *(const float4*)&sxn[tr * 2 + r][k];
            #pragma unroll
            for (int c = 0; c < 8; c++) {
                float4 w = *(const float4*)&f1w[(col0 + c) * 96 + k];
                #pragma unroll
                for (int r = 0; r < 2; r++)
                    acc[r][c] += a[r].x * w.x + a[r].y * w.y +
                                 a[r].z * w.z + a[r].w * w.w;
            }
        }
        #pragma unroll
        for (int c = 0; c < 8; c++) {
            const float bb = f1b[col0 + c];
            #pragma unroll
            for (int r = 0; r < 2; r++) {
                float v = acc[r][c] + bb;
                v = 0.5f * v * (1.f + erff(v * 0.70710678118654752f));
                shh[tr * 2 + r][col0 + c] = v;
            }
        }
    }
    __syncthreads();

    // ---- FC2 (16x384 @ 384x96) + residual, microtile 2x2 -------------------
    {
        const int tr = tid / 48;        // rows tr*2..
        const int tc = tid % 48;        // cols tc*2..
        const int col0 = tc * 2;
        float acc[2][2];
        acc[0][0] = acc[0][1] = acc[1][0] = acc[1][1] = 0.f;

        #pragma unroll 1
        for (int k = 0; k < HID_; k += 4) {
            float4 a[2];
            #pragma unroll
            for (int r = 0; r < 2; r++)
                a[r] = *(const float4*)&shh[tr * 2 + r][k];
            float4 w0 = *(const float4*)&f2w[(col0 + 0) * 384 + k];
            float4 w1 = *(const float4*)&f2w[(col0 + 1) * 384 + k];
            #pragma unroll
            for (int r = 0; r < 2; r++) {
                acc[r][0] += a[r].x * w0.x + a[r].y * w0.y + a[r].z * w0.z + a[r].w * w0.w;
                acc[r][1] += a[r].x * w1.x + a[r].y * w1.y + a[r].z * w1.z + a[r].w * w1.w;
            }
        }
        const float b0 = f2b[col0], b1 = f2b[col0 + 1];
        #pragma unroll
        for (int r = 0; r < 2; r++) {
            const size_t tok = (size_t)(t0 + tr * 2 + r);
            out[tok * C_ + col0 + 0] = g_x1[tok * C_ + col0 + 0] + acc[r][0] + b0;
            out[tok * C_ + col0 + 1] = g_x1[tok * C_ + col0 + 1] + acc[r][1] + b1;
        }
    }
}

// ---------------------------------------------------------------------------
extern "C" void kernel_launch(void* const* d_in, const int* in_sizes, int n_in,
                              void* d_out, int out_size)
{
    const float* x         = (const float*)d_in[0];
    const float* attn_mask = (const float*)d_in[1];
    const int*   rel_index = (const int*)  d_in[2];
    const float* n1g       = (const float*)d_in[3];
    const float* n1b       = (const float*)d_in[4];
    const float* qkvw      = (const float*)d_in[5];
    const float* qkvb      = (const float*)d_in[6];
    const float* pw        = (const float*)d_in[7];
    const float* pb        = (const float*)d_in[8];
    const float* relt      = (const float*)d_in[9];
    const float* n2g       = (const float*)d_in[10];
    const float* n2b       = (const float*)d_in[11];
    const float* f1w       = (const float*)d_in[12];
    const float* f1b       = (const float*)d_in[13];
    const float* f2w       = (const float*)d_in[14];
    const float* f2b       = (const float*)d_in[15];
    float* out = (float*)d_out;

    k1_ln_qkv<<<NWIN, 512>>>(x, n1g, n1b, qkvw, qkvb);
    k2_attn<<<dim3(NWIN, NH_), 64>>>(attn_mask, rel_index, relt);
    k3_proj<<<NWIN, 192>>>(x, pw, pb);
    k4_mlp<<<TOK / 16, 384>>>(n2g, n2b, f1w, f1b, f2w, f2b, out);
}

// round 4
// speedup vs baseline: 2.7422x; 2.7422x over previous
#include <cuda_runtime.h>
#include <math.h>

// Swin block: B=32, H=W=112, C=96, NH=3, WS=7, SHIFT=3
#define B_      32
#define H_      112
#define W_      112
#define C_      96
#define NH_     3
#define WS_     7
#define SHIFT_  3
#define N_      49          // WS*WS
#define HD_     32          // C/NH
#define NW_IMG  256         // per-image windows
#define NWIN    8192        // B * NW_IMG
#define TOK     401408      // B*H*W
#define HID_    384

// ---------------- scratch (device globals; no allocations allowed) ---------
__device__ float g_qkv[(size_t)3 * NWIN * NH_ * N_ * HD_];   // q | k | v
__device__ float g_ao[(size_t)NWIN * N_ * C_];               // head-merged attn output
__device__ float g_x1[(size_t)TOK * C_];                     // shortcut + attn branch
__device__ float g_h [(size_t)TOK * HID_];                   // GELU(FC1) activations

#define QKV_SEG ((size_t)NWIN * NH_ * N_ * HD_)

// ---------------------------------------------------------------------------
// K1: LN1 + shift + window partition + QKV GEMM (49x96 @ 96x288)
// 256 threads/block. Weights staged transposed in smem, 4 col-tiles of 72.
// ---------------------------------------------------------------------------
__global__ __launch_bounds__(256) void k1_ln_qkv(
    const float* __restrict__ x,
    const float* __restrict__ n1g, const float* __restrict__ n1b,
    const float* __restrict__ qkv_w, const float* __restrict__ qkv_b)
{
    __shared__ float sx[N_][C_];        // 18816 B
    __shared__ float swt[C_][72];       // 27648 B (transposed weight tile)
    const int win = blockIdx.x;
    const int b = win >> 8;
    const int wi = win & 255;
    const int wh = wi >> 4, ww = wi & 15;
    const int tid = threadIdx.x;
    const int warp = tid >> 5, lane = tid & 31;

    // ---- LN1 -------------------------------------------------------------
    for (int n = warp; n < N_; n += 8) {
        const int i = n / 7, j = n % 7;
        const int sh = (wh * 7 + i + SHIFT_) % H_;
        const int sw = (ww * 7 + j + SHIFT_) % W_;
        const float* row = x + (size_t)(b * H_ * W_ + sh * W_ + sw) * C_;
        float v0 = row[lane], v1 = row[lane + 32], v2 = row[lane + 64];
        float s = v0 + v1 + v2;
        float ss = v0 * v0 + v1 * v1 + v2 * v2;
        #pragma unroll
        for (int o = 16; o > 0; o >>= 1) {
            s  += __shfl_xor_sync(0xffffffffu, s, o);
            ss += __shfl_xor_sync(0xffffffffu, ss, o);
        }
        const float mean = s * (1.f / 96.f);
        const float var  = ss * (1.f / 96.f) - mean * mean;
        const float rstd = rsqrtf(var + 1e-5f);
        sx[n][lane]      = (v0 - mean) * rstd * n1g[lane]      + n1b[lane];
        sx[n][lane + 32] = (v1 - mean) * rstd * n1g[lane + 32] + n1b[lane + 32];
        sx[n][lane + 64] = (v2 - mean) * rstd * n1g[lane + 64] + n1b[lane + 64];
    }
    __syncthreads();

    const int tr = tid / 36;            // 0..7 (row group; <7 valid)
    const int tc = tid % 36;            // col pair within tile
    const bool act = (tid < 252);

    for (int ct = 0; ct < 4; ct++) {
        // load transposed weight tile: swt[k][c] = qkv_w[(ct*72+c)*96 + k]
        for (int idx = tid; idx < 72 * 24; idx += 256) {
            const int c = idx / 24, kc = idx % 24;
            float4 w = *(const float4*)&qkv_w[(ct * 72 + c) * C_ + kc * 4];
            swt[kc * 4 + 0][c] = w.x;
            swt[kc * 4 + 1][c] = w.y;
            swt[kc * 4 + 2][c] = w.z;
            swt[kc * 4 + 3][c] = w.w;
        }
        __syncthreads();

        if (act) {
            float acc[7][2];
            #pragma unroll
            for (int r = 0; r < 7; r++) { acc[r][0] = 0.f; acc[r][1] = 0.f; }

            #pragma unroll 2
            for (int kc = 0; kc < 24; kc++) {
                float4 a[7];
                #pragma unroll
                for (int r = 0; r < 7; r++)
                    a[r] = *(const float4*)&sx[tr * 7 + r][kc * 4];
                #pragma unroll
                for (int i = 0; i < 4; i++) {
                    const int kk = kc * 4 + i;
                    const float w0 = swt[kk][tc * 2 + 0];
                    const float w1 = swt[kk][tc * 2 + 1];
                    #pragma unroll
                    for (int r = 0; r < 7; r++) {
                        const float av = (i == 0) ? a[r].x : (i == 1) ? a[r].y :
                                         (i == 2) ? a[r].z : a[r].w;
                        acc[r][0] += av * w0;
                        acc[r][1] += av * w1;
                    }
                }
            }

            #pragma unroll
            for (int c = 0; c < 2; c++) {
                const int col = ct * 72 + tc * 2 + c;
                const int which = col / 96;            // 0=q 1=k 2=v
                const int head = (col % 96) / 32;
                const int hd = col & 31;
                const float bb = qkv_b[col];
                const float scale = (which == 0) ? 0.17677669529663687f : 1.f;
                float* dst = g_qkv + (size_t)which * QKV_SEG;
                const size_t base = ((size_t)win * NH_ + head) * N_ * HD_ + hd;
                #pragma unroll
                for (int r = 0; r < 7; r++)
                    dst[base + (size_t)(tr * 7 + r) * HD_] = (acc[r][c] + bb) * scale;
            }
        }
        __syncthreads();
    }
}

// ---------------------------------------------------------------------------
// K2: attention per (window, head). 64 threads; thread i = query row i.
// ---------------------------------------------------------------------------
__global__ __launch_bounds__(64) void k2_attn(
    const float* __restrict__ attn_mask,
    const int* __restrict__ rel_index,
    const float* __restrict__ rel_tab)
{
    __shared__ float sk[N_][HD_];
    __shared__ float sv[N_][HD_];
    __shared__ float sbm[N_][N_];     // bias + mask
    const int win = blockIdx.x;
    const int head = blockIdx.y;
    const int tid = threadIdx.x;

    const float* kp = g_qkv + QKV_SEG + ((size_t)win * NH_ + head) * N_ * HD_;
    const float* vp = g_qkv + 2 * QKV_SEG + ((size_t)win * NH_ + head) * N_ * HD_;
    for (int i = tid; i < N_ * HD_ / 4; i += 64) {
        ((float4*)&sk[0][0])[i] = ((const float4*)kp)[i];
        ((float4*)&sv[0][0])[i] = ((const float4*)vp)[i];
    }
    const float* mp = attn_mask + (size_t)(win & 255) * N_ * N_;
    for (int i = tid; i < N_ * N_; i += 64)
        (&sbm[0][0])[i] = rel_tab[rel_index[i] * NH_ + head] + mp[i];
    __syncthreads();

    if (tid >= N_) return;
    const float* qp = g_qkv + (((size_t)win * NH_ + head) * N_ + tid) * HD_;
    float q[HD_];
    #pragma unroll
    for (int d = 0; d < HD_; d += 4) {
        float4 qq = *(const float4*)&qp[d];
        q[d] = qq.x; q[d+1] = qq.y; q[d+2] = qq.z; q[d+3] = qq.w;
    }

    float s[N_];
    float mx = -1e30f;
    #pragma unroll
    for (int j = 0; j < N_; j++) {
        float acc = sbm[tid][j];
        #pragma unroll
        for (int d = 0; d < HD_; d++) acc += q[d] * sk[j][d];
        s[j] = acc;
        mx = fmaxf(mx, acc);
    }
    float denom = 0.f;
    #pragma unroll
    for (int j = 0; j < N_; j++) { s[j] = __expf(s[j] - mx); denom += s[j]; }
    const float inv = 1.f / denom;

    float o[HD_];
    #pragma unroll
    for (int d = 0; d < HD_; d++) o[d] = 0.f;
    #pragma unroll
    for (int j = 0; j < N_; j++) {
        const float p = s[j];
        #pragma unroll
        for (int d = 0; d < HD_; d++) o[d] += p * sv[j][d];
    }
    float* op = g_ao + ((size_t)win * N_ + tid) * C_ + head * HD_;
    #pragma unroll
    for (int d = 0; d < HD_; d++) op[d] = o[d] * inv;
}

// ---------------------------------------------------------------------------
// K3: proj GEMM (49x96 @ 96x96) + window reverse + unshift + residual -> x1
// 192 threads. Transposed weight tiles of 48 cols (2 tiles).
// ---------------------------------------------------------------------------
__global__ __launch_bounds__(192) void k3_proj(
    const float* __restrict__ x,
    const float* __restrict__ proj_w, const float* __restrict__ proj_b)
{
    __shared__ float sa[N_][C_];        // 18816 B
    __shared__ float swt[C_][48];       // 18432 B
    const int win = blockIdx.x;
    const int b = win >> 8;
    const int wi = win & 255;
    const int wh = wi >> 4, ww = wi & 15;
    const int tid = threadIdx.x;

    const float* ap = g_ao + (size_t)win * N_ * C_;
    for (int i = tid; i < N_ * C_ / 4; i += 192)
        ((float4*)&sa[0][0])[i] = ((const float4*)ap)[i];
    __syncthreads();

    const int tr = tid / 24;            // row group (<7 valid)
    const int tc = tid % 24;            // col pair
    const bool act = (tid < 168);

    for (int ct = 0; ct < 2; ct++) {
        for (int idx = tid; idx < 48 * 24; idx += 192) {
            const int c = idx / 24, kc = idx % 24;
            float4 w = *(const float4*)&proj_w[(ct * 48 + c) * C_ + kc * 4];
            swt[kc * 4 + 0][c] = w.x;
            swt[kc * 4 + 1][c] = w.y;
            swt[kc * 4 + 2][c] = w.z;
            swt[kc * 4 + 3][c] = w.w;
        }
        __syncthreads();

        if (act) {
            float acc[7][2];
            #pragma unroll
            for (int r = 0; r < 7; r++) { acc[r][0] = 0.f; acc[r][1] = 0.f; }

            #pragma unroll 2
            for (int kc = 0; kc < 24; kc++) {
                float4 a[7];
                #pragma unroll
                for (int r = 0; r < 7; r++)
                    a[r] = *(const float4*)&sa[tr * 7 + r][kc * 4];
                #pragma unroll
                for (int i = 0; i < 4; i++) {
                    const int kk = kc * 4 + i;
                    const float w0 = swt[kk][tc * 2 + 0];
                    const float w1 = swt[kk][tc * 2 + 1];
                    #pragma unroll
                    for (int r = 0; r < 7; r++) {
                        const float av = (i == 0) ? a[r].x : (i == 1) ? a[r].y :
                                         (i == 2) ? a[r].z : a[r].w;
                        acc[r][0] += av * w0;
                        acc[r][1] += av * w1;
                    }
                }
            }

            #pragma unroll
            for (int r = 0; r < 7; r++) {
                const int n = tr * 7 + r;
                const int i = n / 7, j = n % 7;
                const int sh = (wh * 7 + i + SHIFT_) % H_;
                const int sw = (ww * 7 + j + SHIFT_) % W_;
                const size_t tok = (size_t)(b * H_ * W_ + sh * W_ + sw);
                const int col = ct * 48 + tc * 2;
                float2 xr = *(const float2*)&x[tok * C_ + col];
                float2 o;
                o.x = xr.x + acc[r][0] + proj_b[col + 0];
                o.y = xr.y + acc[r][1] + proj_b[col + 1];
                *(float2*)&g_x1[tok * C_ + col] = o;
            }
        }
        __syncthreads();
    }
}

// ---------------------------------------------------------------------------
// K4a: LN2 + FC1 + GELU -> g_h.  64 tokens/block, 256 threads.
// smem: sxn 24576 + swt 18432 = 43008 B static. 8 col-tiles of 48.
// ---------------------------------------------------------------------------
__global__ __launch_bounds__(256) void k4a_fc1(
    const float* __restrict__ n2g, const float* __restrict__ n2b,
    const float* __restrict__ f1w, const float* __restrict__ f1b)
{
    __shared__ float sxn[64][C_];       // LN2 output
    __shared__ float swt[C_][48];       // transposed FC1 weight tile
    const int t0 = blockIdx.x * 64;
    const int tid = threadIdx.x;
    const int warp = tid >> 5, lane = tid & 31;   // 8 warps

    // ---- LN2 -------------------------------------------------------------
    for (int t = warp; t < 64; t += 8) {
        const float* row = g_x1 + (size_t)(t0 + t) * C_;
        float v0 = row[lane], v1 = row[lane + 32], v2 = row[lane + 64];
        float s = v0 + v1 + v2;
        float ss = v0 * v0 + v1 * v1 + v2 * v2;
        #pragma unroll
        for (int o = 16; o > 0; o >>= 1) {
            s  += __shfl_xor_sync(0xffffffffu, s, o);
            ss += __shfl_xor_sync(0xffffffffu, ss, o);
        }
        const float mean = s * (1.f / 96.f);
        const float var  = ss * (1.f / 96.f) - mean * mean;
        const float rstd = rsqrtf(var + 1e-5f);
        sxn[t][lane]      = (v0 - mean) * rstd * n2g[lane]      + n2b[lane];
        sxn[t][lane + 32] = (v1 - mean) * rstd * n2g[lane + 32] + n2b[lane + 32];
        sxn[t][lane + 64] = (v2 - mean) * rstd * n2g[lane + 64] + n2b[lane + 64];
    }
    __syncthreads();

    const int rg = tid / 16;            // 16 row groups (rows rg*4..)
    const int cg = tid % 16;            // 16 col groups (cols cg*3..)

    for (int ct = 0; ct < 8; ct++) {
        for (int idx = tid; idx < 48 * 24; idx += 256) {
            const int c = idx / 24, kc = idx % 24;
            float4 w = *(const float4*)&f1w[(ct * 48 + c) * C_ + kc * 4];
            swt[kc * 4 + 0][c] = w.x;
            swt[kc * 4 + 1][c] = w.y;
            swt[kc * 4 + 2][c] = w.z;
            swt[kc * 4 + 3][c] = w.w;
        }
        __syncthreads();

        float acc[4][3];
        #pragma unroll
        for (int r = 0; r < 4; r++)
            #pragma unroll
            for (int c = 0; c < 3; c++) acc[r][c] = 0.f;

        #pragma unroll 2
        for (int kc = 0; kc < 24; kc++) {
            float4 a[4];
            #pragma unroll
            for (int r = 0; r < 4; r++)
                a[r] = *(const float4*)&sxn[rg * 4 + r][kc * 4];
            #pragma unroll
            for (int i = 0; i < 4; i++) {
                const int kk = kc * 4 + i;
                const float w0 = swt[kk][cg * 3 + 0];
                const float w1 = swt[kk][cg * 3 + 1];
                const float w2 = swt[kk][cg * 3 + 2];
                #pragma unroll
                for (int r = 0; r < 4; r++) {
                    const float av = (i == 0) ? a[r].x : (i == 1) ? a[r].y :
                                     (i == 2) ? a[r].z : a[r].w;
                    acc[r][0] += av * w0;
                    acc[r][1] += av * w1;
                    acc[r][2] += av * w2;
                }
            }
        }

        #pragma unroll
        for (int c = 0; c < 3; c++) {
            const int col = ct * 48 + cg * 3 + c;
            const float bb = f1b[col];
            #pragma unroll
            for (int r = 0; r < 4; r++) {
                float v = acc[r][c] + bb;
                v = 0.5f * v * (1.f + erff(v * 0.70710678118654752f));
                g_h[(size_t)(t0 + rg * 4 + r) * HID_ + col] = v;
            }
        }
        __syncthreads();
    }
}

// ---------------------------------------------------------------------------
// K4b: FC2 (TOKx384 @ 384x96) + residual -> out.  32 tokens/block, 256 thr.
// smem: sh 12288 + swt 18432 = 30720 B static. 4 k-tiles x 2 col-tiles.
// ---------------------------------------------------------------------------
__global__ __launch_bounds__(256) void k4b_fc2(
    const float* __restrict__ f2w, const float* __restrict__ f2b,
    float* __restrict__ out)
{
    __shared__ float sh[32][C_];        // activation k-slice (32 x 96)
    __shared__ float swt[C_][48];       // transposed FC2 weight tile
    const int t0 = blockIdx.x * 32;
    const int tid = threadIdx.x;

    const int rg = tid / 16;            // 16 row groups (rows rg*2..)
    const int cg = tid % 16;            // 16 col groups (cols cg*3 within tile)

    float acc[2][6];                    // [row][ct*3 + c]
    #pragma unroll
    for (int r = 0; r < 2; r++)
        #pragma unroll
        for (int c = 0; c < 6; c++) acc[r][c] = 0.f;

    for (int kt = 0; kt < 4; kt++) {
        // load activation slice: sh[r][kk] = g_h[(t0+r)*384 + kt*96 + kk]
        for (int idx = tid; idx < 32 * 24; idx += 256) {
            const int r = idx / 24, kc = idx % 24;
            float4 a = *(const float4*)&g_h[(size_t)(t0 + r) * HID_ + kt * 96 + kc * 4];
            *(float4*)&sh[r][kc * 4] = a;
        }

        for (int ct = 0; ct < 2; ct++) {
            for (int idx = tid; idx < 48 * 24; idx += 256) {
                const int c = idx / 24, kc = idx % 24;
                float4 w = *(const float4*)&f2w[(ct * 48 + c) * HID_ + kt * 96 + kc * 4];
                swt[kc * 4 + 0][c] = w.x;
                swt[kc * 4 + 1][c] = w.y;
                swt[kc * 4 + 2][c] = w.z;
                swt[kc * 4 + 3][c] = w.w;
            }
            __syncthreads();

            #pragma unroll 2
            for (int kc = 0; kc < 24; kc++) {
                float4 a[2];
                #pragma unroll
                for (int r = 0; r < 2; r++)
                    a[r] = *(const float4*)&sh[rg * 2 + r][kc * 4];
                #pragma unroll
                for (int i = 0; i < 4; i++) {
                    const int kk = kc * 4 + i;
                    const float w0 = swt[kk][cg * 3 + 0];
                    const float w1 = swt[kk][cg * 3 + 1];
                    const float w2 = swt[kk][cg * 3 + 2];
                    #pragma unroll
                    for (int r = 0; r < 2; r++) {
                        const float av = (i == 0) ? a[r].x : (i == 1) ? a[r].y :
                                         (i == 2) ? a[r].z : a[r].w;
                        acc[r][ct * 3 + 0] += av * w0;
                        acc[r][ct * 3 + 1] += av * w1;
                        acc[r][ct * 3 + 2] += av * w2;
                    }
                }
            }
            __syncthreads();
        }
    }

    // bias + residual + store
    #pragma unroll
    for (int ct = 0; ct < 2; ct++) {
        #pragma unroll
        for (int c = 0; c < 3; c++) {
            const int col = ct * 48 + cg * 3 + c;
            const float bb = f2b[col];
            #pragma unroll
            for (int r = 0; r < 2; r++) {
                const size_t tok = (size_t)(t0 + rg * 2 + r);
                out[tok * C_ + col] = g_x1[tok * C_ + col] + acc[r][ct * 3 + c] + bb;
            }
        }
    }
}

// ---------------------------------------------------------------------------
extern "C" void kernel_launch(void* const* d_in, const int* in_sizes, int n_in,
                              void* d_out, int out_size)
{
    const float* x         = (const float*)d_in[0];
    const float* attn_mask = (const float*)d_in[1];
    const int*   rel_index = (const int*)  d_in[2];
    const float* n1g       = (const float*)d_in[3];
    const float* n1b       = (const float*)d_in[4];
    const float* qkvw      = (const float*)d_in[5];
    const float* qkvb      = (const float*)d_in[6];
    const float* pw        = (const float*)d_in[7];
    const float* pb        = (const float*)d_in[8];
    const float* relt      = (const float*)d_in[9];
    const float* n2g       = (const float*)d_in[10];
    const float* n2b       = (const float*)d_in[11];
    const float* f1w       = (const float*)d_in[12];
    const float* f1b       = (const float*)d_in[13];
    const float* f2w       = (const float*)d_in[14];
    const float* f2b       = (const float*)d_in[15];
    float* out = (float*)d_out;

    k1_ln_qkv<<<NWIN, 256>>>(x, n1g, n1b, qkvw, qkvb);
    k2_attn<<<dim3(NWIN, NH_), 64>>>(attn_mask, rel_index, relt);
    k3_proj<<<NWIN, 192>>>(x, pw, pb);
    k4a_fc1<<<TOK / 64, 256>>>(n2g, n2b, f1w, f1b);
    k4b_fc2<<<TOK / 32, 256>>>(f2w, f2b, out);
}